// round 6
// baseline (speedup 1.0000x reference)
#include <cuda_runtime.h>

// Inputs (metadata order):
//  0: link_pos_seq   [1024,32,8,3]    f32
//  1: link_rot_seq   [1024,32,8,3,3]  f32
//  2: sphere_centers [8,8,3]          f32
//  3: sphere_radii   [8,8]            f32
//  4: sdf_grid       [256,256,256]    f32
//  5: weight         scalar           f32
// Output: [1024,32] f32

#define GRID_N 256
#define N_LINKS 8
#define N_SPH 8
#define TB 256
#define NWARP (TB / 32)

// Faithfully-rounded t/0.01 (mul + 2 fma Newton correction).
__device__ __forceinline__ float div001(float t) {
    const float q0 = t * 100.0f;
    return fmaf(fmaf(-0.01f, q0, t), 100.0f, q0);
}

__device__ __forceinline__ int vox(float t) {
    int i = (int)floorf(div001(t + 1.28f));
    return min(max(i, 0), GRID_N - 1);
}

__global__ __launch_bounds__(TB, 8)
void voxel_collision_kernel(const float* __restrict__ pos,
                            const float* __restrict__ rot,
                            const float* __restrict__ cen,
                            const float* __restrict__ rad,
                            const float* __restrict__ sdf,
                            const float* __restrict__ wptr,
                            float* __restrict__ out) {
    __shared__ float s_rot[NWARP][288];            // 9 floats x 32 lanes per warp
    __shared__ float s_pos[NWARP][96];             // 3 floats x 32 lanes per warp
    __shared__ float s_cen[N_LINKS * N_SPH * 3];   // 768 B
    __shared__ float s_rad[N_LINKS * N_SPH];       // 256 B

    const int tid  = threadIdx.x;
    const int w    = tid >> 5;
    const int lane = tid & 31;

    if (tid < N_LINKS * N_SPH * 3) s_cen[tid] = cen[tid];
    if (tid < N_LINKS * N_SPH)     s_rad[tid] = rad[tid];
    __syncthreads();   // covers s_cen/s_rad only; warp slabs are warp-private

    const int gwarp = blockIdx.x * TB + w * 32;    // first item of this warp
    const int g = gwarp + lane;
    const int l = g & 7;

    // ---- warp-cooperative coalesced staging: 12 LDGs, 1 line each ----
    {
        const float* slabR = rot + (size_t)gwarp * 9;   // 288 consecutive floats
        const float* slabP = pos + (size_t)gwarp * 3;   // 96 consecutive floats
        float tR[9], tP[3];
        #pragma unroll
        for (int i = 0; i < 9; i++) tR[i] = __ldg(slabR + i * 32 + lane);
        #pragma unroll
        for (int i = 0; i < 3; i++) tP[i] = __ldg(slabP + i * 32 + lane);
        #pragma unroll
        for (int i = 0; i < 9; i++) s_rot[w][i * 32 + lane] = tR[i];
        #pragma unroll
        for (int i = 0; i < 3; i++) s_pos[w][i * 32 + lane] = tP[i];
        __syncwarp();
    }

    // stride-9 / stride-3 LDS: gcd(9,32)=gcd(3,32)=1 -> conflict-free
    const float r00 = s_rot[w][lane * 9 + 0], r01 = s_rot[w][lane * 9 + 1], r02 = s_rot[w][lane * 9 + 2];
    const float r10 = s_rot[w][lane * 9 + 3], r11 = s_rot[w][lane * 9 + 4], r12 = s_rot[w][lane * 9 + 5];
    const float r20 = s_rot[w][lane * 9 + 6], r21 = s_rot[w][lane * 9 + 7], r22 = s_rot[w][lane * 9 + 8];
    const float px = s_pos[w][lane * 3 + 0], py = s_pos[w][lane * 3 + 1], pz = s_pos[w][lane * 3 + 2];

    const float* lc = s_cen + l * (N_SPH * 3);
    const float* lr = s_rad + l * N_SPH;

    // 8 mutually independent gathers; ptxas front-batches the LDGs.
    float m = -3.402823466e+38f;
    #pragma unroll
    for (int s = 0; s < N_SPH; s++) {
        const float cx = lc[s * 3 + 0];
        const float cy = lc[s * 3 + 1];
        const float cz = lc[s * 3 + 2];
        const float x = fmaf(r00, cx, fmaf(r01, cy, fmaf(r02, cz, px)));
        const float y = fmaf(r10, cx, fmaf(r11, cy, fmaf(r12, cz, py)));
        const float z = fmaf(r20, cx, fmaf(r21, cy, fmaf(r22, cz, pz)));
        const float v = __ldg(sdf + ((vox(x) << 16) | (vox(y) << 8) | vox(z)));
        m = fmaxf(m, lr[s] - v);
    }

    // clip(m - 0.01, 0, 0.5) / 0.25
    float res = fminf(fmaxf(m - 0.01f, 0.0f), 0.5f) * 4.0f;

    // sum over the 8 links (adjacent lanes within the warp)
    res += __shfl_xor_sync(0xffffffffu, res, 1);
    res += __shfl_xor_sync(0xffffffffu, res, 2);
    res += __shfl_xor_sync(0xffffffffu, res, 4);

    if (l == 0) out[g >> 3] = __ldg(wptr) * res;
}

extern "C" void kernel_launch(void* const* d_in, const int* in_sizes, int n_in,
                              void* d_out, int out_size) {
    const float* pos = (const float*)d_in[0];
    const float* rot = (const float*)d_in[1];
    const float* cen = (const float*)d_in[2];
    const float* rad = (const float*)d_in[3];
    const float* sdf = (const float*)d_in[4];
    const float* w   = (const float*)d_in[5];
    float* out = (float*)d_out;

    voxel_collision_kernel<<<1024, TB>>>(pos, rot, cen, rad, sdf, w, out);
}

// round 7
// speedup vs baseline: 1.0152x; 1.0152x over previous
#include <cuda_runtime.h>

// Inputs (metadata order):
//  0: link_pos_seq   [1024,32,8,3]    f32   (per bh: 24 floats)
//  1: link_rot_seq   [1024,32,8,3,3]  f32   (per bh: 72 floats)
//  2: sphere_centers [8,8,3]          f32
//  3: sphere_radii   [8,8]            f32
//  4: sdf_grid       [256,256,256]    f32
//  5: weight         scalar           f32
// Output: [1024,32] f32

#define GRID_N 256
#define N_LINKS 8
#define N_SPH 8
#define TB 256
#define NWARP (TB / 32)

// Faithfully-rounded t/0.01 (mul + 2 fma Newton correction).
__device__ __forceinline__ float div001(float t) {
    const float q0 = t * 100.0f;
    return fmaf(fmaf(-0.01f, q0, t), 100.0f, q0);
}

__device__ __forceinline__ int vox(float t) {
    int i = (int)floorf(div001(t + 1.28f));
    return min(max(i, 0), GRID_N - 1);
}

__global__ __launch_bounds__(TB, 8)
void voxel_collision_kernel(const float* __restrict__ pos,
                            const float* __restrict__ rot,
                            const float* __restrict__ cen,
                            const float* __restrict__ rad,
                            const float* __restrict__ sdf,
                            const float* __restrict__ wptr,
                            float* __restrict__ out) {
    __shared__ float s_stage[NWARP][96];     // per-warp: 72 rot + 24 pos
    __shared__ float s_cen[N_SPH * N_LINKS * 3]; // transposed [s][l][3]
    __shared__ float s_rad[N_SPH * N_LINKS];     // transposed [s][l]

    const int tid  = threadIdx.x;
    const int w    = tid >> 5;
    const int lane = tid & 31;

    // transpose sphere constants to [s][l] so LDS reads are conflict-free
    if (tid < N_LINKS * N_SPH * 3) {
        const int l = tid / 24, s = (tid % 24) / 3, c = tid % 3;
        s_cen[(s * N_LINKS + l) * 3 + c] = cen[tid];
    }
    if (tid < N_LINKS * N_SPH) {
        const int l = tid >> 3, s = tid & 7;
        s_rad[s * N_LINKS + l] = rad[tid];
    }
    __syncthreads();

    const int bh = blockIdx.x * NWARP + w;   // one warp per (b,h), 32768 total

    // ---- 3 fully coalesced LDGs stage this bh's 96-float slab ----
    {
        const float* rb = rot + (size_t)bh * 72;
        const float* pb = pos + (size_t)bh * 24;
        const float t0 = __ldg(rb + lane);
        const float t1 = __ldg(rb + 32 + lane);
        const float t2 = (lane < 8) ? __ldg(rb + 64 + lane) : __ldg(pb + lane - 8);
        s_stage[w][lane]      = t0;
        s_stage[w][32 + lane] = t1;
        s_stage[w][64 + lane] = t2;   // lane>=8 lands at 72 + (lane-8)
        __syncwarp();
    }

    const int l  = lane >> 2;   // link 0..7
    const int s0 = lane & 3;    // sphere pair base

    const float* S = s_stage[w];
    // 4 lanes share each address -> broadcast; 8 distinct addrs stride 9 -> conflict-free
    const float r00 = S[l * 9 + 0], r01 = S[l * 9 + 1], r02 = S[l * 9 + 2];
    const float r10 = S[l * 9 + 3], r11 = S[l * 9 + 4], r12 = S[l * 9 + 5];
    const float r20 = S[l * 9 + 6], r21 = S[l * 9 + 7], r22 = S[l * 9 + 8];
    const float px = S[72 + l * 3 + 0], py = S[72 + l * 3 + 1], pz = S[72 + l * 3 + 2];

    // ---- two independent gathers (spheres s0 and s0+4 of link l) ----
    int off[2];
    float rr[2];
    #pragma unroll
    for (int k = 0; k < 2; k++) {
        const int s = s0 + k * 4;
        const float* c3 = s_cen + (s * N_LINKS + l) * 3;
        const float cx = c3[0], cy = c3[1], cz = c3[2];
        const float x = fmaf(r00, cx, fmaf(r01, cy, fmaf(r02, cz, px)));
        const float y = fmaf(r10, cx, fmaf(r11, cy, fmaf(r12, cz, py)));
        const float z = fmaf(r20, cx, fmaf(r21, cy, fmaf(r22, cz, pz)));
        off[k] = (vox(x) << 16) | (vox(y) << 8) | vox(z);
        rr[k] = s_rad[s * N_LINKS + l];
    }
    float m = fmaxf(rr[0] - __ldg(sdf + off[0]),
                    rr[1] - __ldg(sdf + off[1]));

    // max over spheres: partners differ in lane bits 0,1
    m = fmaxf(m, __shfl_xor_sync(0xffffffffu, m, 1));
    m = fmaxf(m, __shfl_xor_sync(0xffffffffu, m, 2));

    // per-link cost, then sum over links (lane bits 2,3,4)
    float res = fminf(fmaxf(m - 0.01f, 0.0f), 0.5f) * 4.0f;
    res += __shfl_xor_sync(0xffffffffu, res, 4);
    res += __shfl_xor_sync(0xffffffffu, res, 8);
    res += __shfl_xor_sync(0xffffffffu, res, 16);

    if (lane == 0) out[bh] = __ldg(wptr) * res;
}

extern "C" void kernel_launch(void* const* d_in, const int* in_sizes, int n_in,
                              void* d_out, int out_size) {
    const float* pos = (const float*)d_in[0];
    const float* rot = (const float*)d_in[1];
    const float* cen = (const float*)d_in[2];
    const float* rad = (const float*)d_in[3];
    const float* sdf = (const float*)d_in[4];
    const float* w   = (const float*)d_in[5];
    float* out = (float*)d_out;

    // 32768 (b,h) items, one warp each, 8 warps per block -> 4096 blocks
    voxel_collision_kernel<<<4096, TB>>>(pos, rot, cen, rad, sdf, w, out);
}